// round 10
// baseline (speedup 1.0000x reference)
#include <cuda_runtime.h>

#define N_EMB   512
#define EMB_D   64
#define HWSZ    4096
#define NTOK    131072
#define TPB     384
#define TOKS_PER_CHUNK (TPB * 2)          // 768 tokens per chunk
#define NCHUNK  171                       // 170 full + 1 partial (512 tokens)
#define GRID_A  148
#define NREP    8

// Output packing (float32, reference tuple order)
#define OFF_RES 0ULL
#define OFF_ARG 8388608ULL
#define OFF_W   8519680ULL
#define OFF_CS  8552448ULL
#define OFF_EA  8552960ULL

#define SMEM_BYTES ((N_EMB * EMB_D + 2 * N_EMB) * 4)   // codebook + ww + finalize scratch

__device__ float g_histR[NREP][N_EMB];
__device__ float g_esumR[NREP][EMB_D * N_EMB];
__device__ float g_ww[N_EMB];
__device__ float g_wt[N_EMB * EMB_D];   // weight transposed: [j][d]
__device__ unsigned int g_work;
__device__ unsigned int g_done;

__device__ __forceinline__ unsigned long long ffma2(unsigned long long a,
                                                    unsigned long long b,
                                                    unsigned long long c) {
    unsigned long long d;
    asm("fma.rn.f32x2 %0, %1, %2, %3;" : "=l"(d) : "l"(a), "l"(b), "l"(c));
    return d;
}

__device__ __forceinline__ unsigned long long fadd2(unsigned long long a,
                                                    unsigned long long b) {
    unsigned long long d;
    asm("add.rn.f32x2 %0, %1, %2;" : "=l"(d) : "l"(a), "l"(b));
    return d;
}

__device__ __forceinline__ unsigned long long pack2(float lo, float hi) {
    unsigned long long r;
    asm("mov.b64 %0, {%1, %2};" : "=l"(r)
        : "r"(__float_as_uint(lo)), "r"(__float_as_uint(hi)));
    return r;
}

__device__ __forceinline__ void unpack2(unsigned long long v, float& lo, float& hi) {
    unsigned int a, b;
    asm("mov.b64 {%0, %1}, %2;" : "=r"(a), "=r"(b) : "l"(v));
    lo = __uint_as_float(a);
    hi = __uint_as_float(b);
}

// ---------------------------------------------------------------------------
// prep: zero replicated scratch, transpose weight, ||w||^2, reset counters
// ---------------------------------------------------------------------------
__global__ void prep_kernel(const float* __restrict__ w) {
    int idx = blockIdx.x * blockDim.x + threadIdx.x;   // 0..32767
    if (idx == 0) { g_work = 0u; g_done = 0u; }
    if (idx < EMB_D * N_EMB) {
        #pragma unroll
        for (int r = 0; r < NREP; r++) g_esumR[r][idx] = 0.0f;
        int j = idx >> 6;
        int d = idx & 63;
        g_wt[idx] = w[d * N_EMB + j];
    }
    if (idx < N_EMB) {
        #pragma unroll
        for (int r = 0; r < NREP; r++) g_histR[r][idx] = 0.0f;
        float s = 0.0f;
        #pragma unroll
        for (int d = 0; d < EMB_D; d++) {
            float v = w[d * N_EMB + idx];
            s = __fadd_rn(s, __fmul_rn(v, v));
        }
        g_ww[idx] = s;
    }
}

// ---------------------------------------------------------------------------
// assign: 384 thr (3 warps/SMSP), T=2 tokens/thread, J=1 codeword/iter
// to fit ~160 regs. Persistent work-steal, warp-agg hist, NREP esum.
// ---------------------------------------------------------------------------
extern __shared__ float smem_dyn[];

__global__ void __launch_bounds__(TPB, 1)
assign_kernel(const float* __restrict__ x,
              const float* __restrict__ cs_in,
              const float* __restrict__ ea_in,
              float* __restrict__ out) {
    float* w_s  = smem_dyn;                     // [512][64] j-major
    float* ww_s = smem_dyn + N_EMB * EMB_D;     // [512]
    __shared__ int s_chunk;
    __shared__ unsigned int s_rank;

    int tid  = threadIdx.x;
    int lane = tid & 31;
    int rep  = blockIdx.x & (NREP - 1);
    float* histR = g_histR[rep];
    float* esumR = g_esumR[rep];

    // Stage transposed weight once per CTA: coalesced, conflict-free
    {
        const float4* src = (const float4*)g_wt;
        float4* dst = (float4*)w_s;
        for (int i = tid; i < N_EMB * EMB_D / 4; i += TPB)
            dst[i] = src[i];
        for (int j = tid; j < N_EMB; j += TPB)
            ww_s[j] = g_ww[j];
    }

    for (;;) {
        __syncthreads();
        if (tid == 0) s_chunk = (int)atomicAdd(&g_work, 1u);
        __syncthreads();
        int c = s_chunk;
        if (c >= NCHUNK) break;

        int t0 = c * TOKS_PER_CHUNK + tid;      // token A (always valid)
        int t1 = t0 + TPB;                      // token B (maybe invalid in last chunk)
        bool vB = (t1 < NTOK);
        int t1c = vB ? t1 : (NTOK - 1);

        int b0 = t0 >> 12,  hw0 = t0 & (HWSZ - 1);
        int b1 = t1c >> 12, hw1 = t1c & (HWSZ - 1);
        const float* xa_p = x + (size_t)b0 * EMB_D * HWSZ + hw0;
        const float* xb_p = x + (size_t)b1 * EMB_D * HWSZ + hw1;

        unsigned long long xpa[EMB_D / 2];
        unsigned long long xpb[EMB_D / 2];
        #pragma unroll
        for (int i = 0; i < EMB_D / 2; i++) {
            xpa[i] = pack2(xa_p[(2 * i) * HWSZ], xa_p[(2 * i + 1) * HWSZ]);
            xpb[i] = pack2(xb_p[(2 * i) * HWSZ], xb_p[(2 * i + 1) * HWSZ]);
        }

        float bestA = 3.4e38f, bestB = 3.4e38f;
        int   biA = 0, biB = 0;

        #pragma unroll 1
        for (int j0 = 0; j0 < N_EMB; j0++) {
            const ulonglong2* r = (const ulonglong2*)(w_s + j0 * EMB_D);

            unsigned long long aAe = 0ULL, aAo = 0ULL;
            unsigned long long aBe = 0ULL, aBo = 0ULL;

            #pragma unroll
            for (int q = 0; q < EMB_D / 4; q++) {
                ulonglong2 v = r[q];              // broadcast LDS.128
                aAe = ffma2(xpa[2 * q],     v.x, aAe);
                aAo = ffma2(xpa[2 * q + 1], v.y, aAo);
                aBe = ffma2(xpb[2 * q],     v.x, aBe);
                aBo = ffma2(xpb[2 * q + 1], v.y, aBo);
            }

            float lo, hi;
            float wj = ww_s[j0];
            unpack2(fadd2(aAe, aAo), lo, hi);
            float dA = __fmaf_rn(-2.0f, __fadd_rn(lo, hi), wj);
            unpack2(fadd2(aBe, aBo), lo, hi);
            float dB = __fmaf_rn(-2.0f, __fadd_rn(lo, hi), wj);

            // strict < ascending j => first-min tie-break (jnp.argmin)
            if (dA < bestA) { bestA = dA; biA = j0; }
            if (dB < bestB) { bestB = dB; biB = j0; }
        }

        out[OFF_ARG + (size_t)t0] = (float)biA;
        if (vB) out[OFF_ARG + (size_t)t1] = (float)biB;

        // quantized result from smem codebook (coalesced per d-plane)
        {
            float* ro = out + (size_t)b0 * EMB_D * HWSZ + hw0;
            const float4* wrow = (const float4*)(w_s + biA * EMB_D);
            #pragma unroll
            for (int i = 0; i < EMB_D / 4; i++) {
                float4 v = wrow[i];
                ro[(4 * i + 0) * HWSZ] = v.x;
                ro[(4 * i + 1) * HWSZ] = v.y;
                ro[(4 * i + 2) * HWSZ] = v.z;
                ro[(4 * i + 3) * HWSZ] = v.w;
            }
        }
        if (vB) {
            float* ro = out + (size_t)b1 * EMB_D * HWSZ + hw1;
            const float4* wrow = (const float4*)(w_s + biB * EMB_D);
            #pragma unroll
            for (int i = 0; i < EMB_D / 4; i++) {
                float4 v = wrow[i];
                ro[(4 * i + 0) * HWSZ] = v.x;
                ro[(4 * i + 1) * HWSZ] = v.y;
                ro[(4 * i + 2) * HWSZ] = v.z;
                ro[(4 * i + 3) * HWSZ] = v.w;
            }
        }

        // hist: warp-aggregated
        {
            unsigned int mA = __match_any_sync(0xFFFFFFFFu, biA);
            if ((int)(__ffs(mA) - 1) == lane)
                atomicAdd(&histR[biA], (float)__popc(mA));

            unsigned int act = __ballot_sync(0xFFFFFFFFu, vB);
            if (vB) {
                unsigned int mB = __match_any_sync(0xFFFFFFFFu, biB) & act;
                if ((int)(__ffs(mB) - 1) == lane)
                    atomicAdd(&histR[biB], (float)__popc(mB));
            } else {
                __match_any_sync(0xFFFFFFFFu, biB);   // keep collective uniform
            }
        }

        // esum: replicated accumulators
        #pragma unroll
        for (int i = 0; i < EMB_D / 2; i++) {
            float lo, hi;
            unpack2(xpa[i], lo, hi);
            atomicAdd(&esumR[(2 * i)     * N_EMB + biA], lo);
            atomicAdd(&esumR[(2 * i + 1) * N_EMB + biA], hi);
            if (vB) {
                unpack2(xpb[i], lo, hi);
                atomicAdd(&esumR[(2 * i)     * N_EMB + biB], lo);
                atomicAdd(&esumR[(2 * i + 1) * N_EMB + biB], hi);
            }
        }
    }

    // ------- merged finalize: last CTA does the EMA update -------
    __threadfence();
    __syncthreads();
    if (tid == 0) s_rank = atomicAdd(&g_done, 1u);
    __syncthreads();
    if (s_rank == GRID_A - 1) {
        float* red   = smem_dyn;              // [512] (codebook dead)
        float* ncs_s = smem_dyn + N_EMB;      // [512]

        const float DEC  = 0.99f;
        const float OMD  = (float)(1.0 - 0.99);
        const float EPSF = (float)1e-5;
        const float NEPS = (float)(N_EMB * 1e-5);

        __syncthreads();
        for (int j = tid; j < N_EMB; j += TPB) {
            float n0 = 0.0f;
            #pragma unroll
            for (int r = 0; r < NREP; r++) n0 += g_histR[r][j];
            if (n0 == 0.0f) n0 = 1.0f;
            float ncs = __fadd_rn(__fmul_rn(DEC, cs_in[j]), __fmul_rn(OMD, n0));
            ncs_s[j] = ncs;
            red[j]   = ncs;
        }
        __syncthreads();
        #pragma unroll
        for (int s = N_EMB / 2; s > 0; s >>= 1) {
            if (tid < s) red[tid] += red[tid + s];
            __syncthreads();
        }
        float n = red[0];

        for (int j = tid; j < N_EMB; j += TPB) {
            float ncs = ncs_s[j];
            float csn = __fmul_rn(__fdiv_rn(__fadd_rn(ncs, EPSF),
                                            __fadd_rn(n, NEPS)), n);
            out[OFF_CS + j] = ncs;
            for (int d = 0; d < EMB_D; d++) {
                int idx = d * N_EMB + j;
                float s0 = 0.0f;
                #pragma unroll
                for (int r = 0; r < NREP; r++) s0 += g_esumR[r][idx];
                float e = __fadd_rn(__fmul_rn(DEC, ea_in[idx]),
                                    __fmul_rn(OMD, s0));
                out[OFF_EA + idx] = e;
                out[OFF_W  + idx] = __fdiv_rn(e, csn);
            }
        }
    }
}

// ---------------------------------------------------------------------------
extern "C" void kernel_launch(void* const* d_in, const int* in_sizes, int n_in,
                              void* d_out, int out_size) {
    const float* x  = (const float*)d_in[0];
    const float* w  = (const float*)d_in[1];
    const float* cs = (const float*)d_in[2];
    const float* ea = (const float*)d_in[3];
    float* out = (float*)d_out;

    cudaFuncSetAttribute(assign_kernel,
                         cudaFuncAttributeMaxDynamicSharedMemorySize, SMEM_BYTES);

    prep_kernel<<<128, 256>>>(w);
    assign_kernel<<<GRID_A, TPB, SMEM_BYTES>>>(x, cs, ea, out);
}